// round 13
// baseline (speedup 1.0000x reference)
#include <cuda_runtime.h>
#include <cstdint>
#include <cfloat>
#include <math.h>

#define NPTS 8192
#define DIM 64
#define KNN 90
#define NCAT 8
#define NTRIES 50
#define TOLR 1e-5f
#define WCAP 256     // per-warp candidate cap
#define CCAP 2048    // total candidate cap

// scratch (device globals: allocation-free kernel_launch)
__device__ float g_d2[(size_t)NPTS * NPTS];   // 256 MB pairwise d2 (diagonal = FLT_MAX)
__device__ float g_dist[NPTS * KNN];
__device__ int   g_lab[NPTS * KNN];

// ---------------------------------------------------------------- GEMM stage
#define BM 128
#define BN 128
#define KPAD 65    // 64 + 1 pad: conflict-free LDS for strided frags
#define TPITCH 129 // transpose-stage pitch
#define NTILE 64   // 8192 / 128
#define NTRI  2080 // NTILE*(NTILE+1)/2

// XLA-emulating row norm: jnp.sum(x*x, -1): products individually rounded
// (no fma), float2-vectorized lane partials, then shfl tree.
__device__ __forceinline__ float xla_row_sq(const float* rowp, int lane) {
    float x0 = rowp[2 * lane];
    float x1 = rowp[2 * lane + 1];
    float s = __fadd_rn(__fmul_rn(x0, x0), __fmul_rn(x1, x1));
    #pragma unroll
    for (int off = 16; off > 0; off >>= 1)
        s = __fadd_rn(s, __shfl_down_sync(0xffffffffu, s, off));
    return __shfl_sync(0xffffffffu, s, 0);
}

// Triangular tiles only (bx >= by): d2 is bitwise symmetric
// (fmaf(a,b,c)==fmaf(b,a,c); fadd commutes; same ascending-k order), so the
// off-diagonal mirror tile is written from an smem-staged transpose.
__global__ void __launch_bounds__(256, 2) gemm_d2_kernel(const float* __restrict__ x) {
    extern __shared__ float smem[];
    float* As  = smem;                    // [BM][KPAD]
    float* Bs  = smem + BM * KPAD;        // [BN][KPAD]
    float* sqA = Bs + BN * KPAD;          // [BM]
    float* sqB = sqA + BM;                // [BN]
    float* Ts  = smem;                    // transpose stage, reuses As+Bs

    // linear triangular index -> (by, bx), by <= bx
    const int t = blockIdx.x;
    int by = (int)((129.0 - sqrt(16641.0 - 8.0 * (double)t)) * 0.5);
    while (by > 0 && (by * (129 - by)) / 2 > t) --by;
    while (((by + 1) * (129 - (by + 1))) / 2 <= t) ++by;
    const int bx = by + (t - (by * (129 - by)) / 2);
    const bool mirror = (bx > by);

    const int tid = threadIdx.x;
    const int bm = by * BM;
    const int bn = bx * BN;

    // coalesced global load: float4 per thread, 16 threads cover one 64-col row
    const int c4 = tid & 15;
    const int rb = tid >> 4;
    #pragma unroll
    for (int it = 0; it < 8; ++it) {
        int r = rb + it * 16;
        float4 av = *reinterpret_cast<const float4*>(x + (size_t)(bm + r) * DIM + c4 * 4);
        float4 bv = *reinterpret_cast<const float4*>(x + (size_t)(bn + r) * DIM + c4 * 4);
        float* ap = As + r * KPAD + c4 * 4;
        ap[0] = av.x; ap[1] = av.y; ap[2] = av.z; ap[3] = av.w;
        float* bp = Bs + r * KPAD + c4 * 4;
        bp[0] = bv.x; bp[1] = bv.y; bp[2] = bv.z; bp[3] = bv.w;
    }
    __syncthreads();

    // norms with XLA-matching arithmetic (warp per row)
    {
        const int lane = tid & 31;
        const int wrp  = tid >> 5;
        #pragma unroll
        for (int it = 0; it < 16; ++it) {
            int r = wrp + it * 8;
            float sa = xla_row_sq(As + r * KPAD, lane);
            float sb = xla_row_sq(Bs + r * KPAD, lane);
            if (lane == 0) { sqA[r] = sa; sqB[r] = sb; }
        }
    }
    __syncthreads();

    // 8x8 micro-tile, strided mapping (row = ty+16i, col = tx+16j)
    const int tx = tid & 15;
    const int ty = tid >> 4;

    float acc[8][8];
    #pragma unroll
    for (int i = 0; i < 8; ++i)
        #pragma unroll
        for (int j = 0; j < 8; ++j) acc[i][j] = 0.f;

    // sequential ascending-k fp32 FFMA chain (reference-matching numerics)
    #pragma unroll 8
    for (int k = 0; k < DIM; ++k) {
        float a[8], b[8];
        #pragma unroll
        for (int i = 0; i < 8; ++i) a[i] = As[(ty + 16 * i) * KPAD + k];
        #pragma unroll
        for (int j = 0; j < 8; ++j) b[j] = Bs[(tx + 16 * j) * KPAD + k];
        #pragma unroll
        for (int i = 0; i < 8; ++i)
            #pragma unroll
            for (int j = 0; j < 8; ++j)
                acc[i][j] = fmaf(a[i], b[j], acc[i][j]);
    }
    __syncthreads();   // all warps done reading As/Bs before Ts staging

    #pragma unroll
    for (int i = 0; i < 8; ++i) {
        int m = ty + 16 * i;
        int gm = bm + m;
        float sm = sqA[m];
        float* orow = g_d2 + (size_t)gm * NPTS + bn;
        #pragma unroll
        for (int j = 0; j < 8; ++j) {
            int n = tx + 16 * j;
            float v = __fsub_rn(__fadd_rn(sm, sqB[n]), __fmul_rn(2.f, acc[i][j]));
            v = fmaxf(v, 0.f);
            if (gm == bn + n) v = FLT_MAX;     // exclude self (diag tiles only)
            orow[n] = v;
            if (mirror) Ts[n * TPITCH + m] = v;
        }
    }

    if (mirror) {
        __syncthreads();
        // coalesced mirror write: g_d2[(bn+r), bm+c] = Ts[r][c]
        #pragma unroll
        for (int q = 0; q < 16; ++q) {
            int idx = tid + q * 256;          // 0..4095 (128 rows x 32 float4)
            int r   = idx >> 5;
            int cc  = idx & 31;
            const float* tp = Ts + r * TPITCH + cc * 4;
            float4 v;
            v.x = tp[0]; v.y = tp[1]; v.z = tp[2]; v.w = tp[3];
            *reinterpret_cast<float4*>(g_d2 + (size_t)(bn + r) * NPTS + bm + cc * 4) = v;
        }
    }
}

// ------------------------------------------------------------- select stage
// one block per row, barrier-light. Row loaded once into registers.
// Threshold = exact order statistic of 256 samples found by RANK counting
// (no sort, no barriers). Gather by warp ballot compaction. Emit by RANK
// among unique packed (key,idx) u64 candidates == exact jax.lax.top_k order.
__global__ void __launch_bounds__(256) select_kernel(const int* __restrict__ batch_id) {
    __shared__ unsigned long long candA[8 * WCAP];   // 16 KB
    __shared__ unsigned long long candB[CCAP];       // 16 KB
    __shared__ unsigned samp[256];
    __shared__ unsigned wcnt[8], woff[8];
    __shared__ unsigned s_total, s_T0, s_T1;
    __shared__ int s_fail;
    __shared__ float wv[8];
    __shared__ int   wj[8];

    const int row  = blockIdx.x;
    const int tid  = threadIdx.x;
    const int lane = tid & 31;
    const int wid  = tid >> 5;

    // single coalesced DRAM pass into registers (MLP = 8)
    const uint4* rp = reinterpret_cast<const uint4*>(g_d2 + (size_t)row * NPTS);
    uint4 kreg[8];
    #pragma unroll
    for (int it = 0; it < 8; ++it) kreg[it] = rp[tid + it * 256];

    // --- threshold by rank: publish 8th and 32nd smallest sample ---
    samp[tid] = kreg[0].x;
    __syncthreads();
    {
        unsigned mine = samp[tid];
        int r = 0;
        #pragma unroll 8
        for (int j = 0; j < 256; ++j) {
            unsigned o = samp[j];
            r += (o < mine) || (o == mine && j < tid);
        }
        if (r == 7)  s_T0 = mine;   // E[cands] ~ 255
        if (r == 31) s_T1 = mine;   // E[cands] ~ 1020 (retry)
    }
    __syncthreads();

    // --- gather attempts (ballot compaction, no atomics) ---
    bool ok = false;
    unsigned total = 0;
    for (int attempt = 0; attempt < 2 && !ok; ++attempt) {
        unsigned T = attempt ? s_T1 : s_T0;
        if (tid == 0) s_fail = 0;
        __syncthreads();

        unsigned cnt = 0;
        bool ovf = false;
        #pragma unroll
        for (int it = 0; it < 8; ++it) {
            unsigned kk[4] = { kreg[it].x, kreg[it].y, kreg[it].z, kreg[it].w };
            #pragma unroll
            for (int c = 0; c < 4; ++c) {
                unsigned key = kk[c];
                unsigned j   = 4u * (unsigned)(tid + it * 256) + (unsigned)c;
                bool pred = (key <= T);
                unsigned mask = __ballot_sync(0xffffffffu, pred);
                unsigned rnk = __popc(mask & ((1u << lane) - 1u));
                unsigned n   = __popc(mask);
                if (pred && cnt + rnk < WCAP)
                    candA[wid * WCAP + cnt + rnk] =
                        ((unsigned long long)key << 32) | j;
                if (cnt + n > WCAP) ovf = true;
                cnt = min(cnt + n, (unsigned)WCAP);
            }
        }
        if (lane == 0) { wcnt[wid] = cnt; if (ovf) s_fail = 1; }
        __syncthreads();
        if (tid == 0) {
            unsigned off = 0;
            #pragma unroll
            for (int w = 0; w < 8; ++w) { woff[w] = off; off += wcnt[w]; }
            s_total = off;
        }
        __syncthreads();
        total = s_total;
        ok = (s_fail == 0 && total >= KNN && total <= CCAP);
        if (ok) {
            for (unsigned tt = lane; tt < wcnt[wid]; tt += 32)
                candB[woff[wid] + tt] = candA[wid * WCAP + tt];
        }
        __syncthreads();
    }

    if (ok) {
        // --- rank-based emit: rank = #{strictly smaller u64} = top_k slot ---
        // packed (key<<32|idx) values are unique (idx unique), so ranks are a
        // permutation of 0..total-1; slots < KNN receive exactly the K-NN in
        // exact (value asc, index asc) order.
        unsigned long long mine[8];
        int rk[8];
        int nm = 0;
        for (int i = tid; i < (int)total; i += 256) { mine[nm] = candB[i]; rk[nm] = 0; ++nm; }
        for (int j = 0; j < (int)total; ++j) {
            unsigned long long o = candB[j];   // LDS broadcast
            #pragma unroll
            for (int q = 0; q < 8; ++q)
                if (q < nm && o < mine[q]) ++rk[q];
        }
        #pragma unroll
        for (int q = 0; q < 8; ++q) {
            if (q < nm && rk[q] < KNN) {
                unsigned key = (unsigned)(mine[q] >> 32);
                int idx = (int)(mine[q] & 0xFFFFFFFFu);
                g_dist[row * KNN + rk[q]] = __fsqrt_rn(__uint_as_float(key));
                g_lab[row * KNN + rk[q]]  = batch_id[idx];
            }
        }
        return;
    }

    // --- brute-force fallback (degenerate data only; never taken) ---
    for (int p = 0; p < KNN; ++p) {
        float bv = FLT_MAX; int bj = NPTS;
        #pragma unroll
        for (int it = 0; it < 8; ++it) {
            unsigned kk[4] = { kreg[it].x, kreg[it].y, kreg[it].z, kreg[it].w };
            #pragma unroll
            for (int c = 0; c < 4; ++c) {
                float v = __uint_as_float(kk[c]);
                int j = 4 * (tid + it * 256) + c;
                if (v < bv || (v == bv && j < bj)) { bv = v; bj = j; }
            }
        }
        #pragma unroll
        for (int off = 16; off > 0; off >>= 1) {
            float ov = __shfl_xor_sync(0xffffffffu, bv, off);
            int   oj = __shfl_xor_sync(0xffffffffu, bj, off);
            if (ov < bv || (ov == bv && oj < bj)) { bv = ov; bj = oj; }
        }
        if (lane == 0) { wv[wid] = bv; wj[wid] = bj; }
        __syncthreads();
        if (tid == 0) {
            float fv = wv[0]; int fj = wj[0];
            #pragma unroll
            for (int w = 1; w < 8; ++w)
                if (wv[w] < fv || (wv[w] == fv && wj[w] < fj)) { fv = wv[w]; fj = wj[w]; }
            wj[0] = fj;
            g_dist[row * KNN + p] = __fsqrt_rn(fv);
            g_lab[row * KNN + p]  = batch_id[fj];
        }
        __syncthreads();
        // remove winner (static register indexing only — no spills)
        int fj = wj[0];
        int own_t  = (fj >> 2) & 255;
        int own_it = (fj >> 2) >> 8;
        int own_c  = fj & 3;
        if (tid == own_t) {
            #pragma unroll
            for (int it = 0; it < 8; ++it) {
                if (it == own_it) {
                    if (own_c == 0) kreg[it].x = 0x7F7FFFFFu;
                    if (own_c == 1) kreg[it].y = 0x7F7FFFFFu;
                    if (own_c == 2) kreg[it].z = 0x7F7FFFFFu;
                    if (own_c == 3) kreg[it].w = 0x7F7FFFFFu;
                }
            }
        }
        __syncthreads();
    }
}

// --------------------------------------------------------- beta search stage
__device__ __forceinline__ float warp_sum(float v) {
    #pragma unroll
    for (int o = 16; o > 0; o >>= 1) v += __shfl_xor_sync(0xffffffffu, v, o);
    return v;
}

// FTZ exp: XLA compiles GPU f32 with flush-to-zero — exp results that would be
// subnormal flush to 0. Load-bearing: rows whose solution beta sits past the
// subnormal cliff hit Psum==0 -> H==0 sentinel in the reference.
__device__ __forceinline__ float exp_ftz(float a) {
    float v = expf(a);
    if (v < 1.17549435e-38f) v = 0.f;
    return v;
}

__device__ __forceinline__ void hbeta_eval(const float d[3], const bool val[3],
                                           float beta, float p[3],
                                           float& Psum, float& H) {
    float ls = 0.f, lds = 0.f;
    #pragma unroll
    for (int t = 0; t < 3; ++t) {
        float pv = val[t] ? exp_ftz(-d[t] * beta) : 0.f;
        p[t] = pv;
        ls  += pv;
        lds += d[t] * pv;
    }
    Psum   = warp_sum(ls);
    float S = warp_sum(lds);
    H = (Psum > 0.f) ? (logf(Psum) + beta * __fdiv_rn(S, Psum)) : 0.f;
}

__global__ void __launch_bounds__(128) beta_kernel(float* __restrict__ out) {
    const int warp = threadIdx.x >> 5;
    const int lane = threadIdx.x & 31;
    const int row  = blockIdx.x * 4 + warp;

    float d[3]; int lb[3]; bool val[3];
    #pragma unroll
    for (int t = 0; t < 3; ++t) {
        int kk = lane + 32 * t;
        val[t] = (kk < KNN);
        d[t]  = val[t] ? g_dist[row * KNN + kk] : 0.f;
        lb[t] = val[t] ? g_lab[row * KNN + kk]  : -1;
    }

    const float logU = logf(30.0f);
    float beta = 1.f, bmin = 0.f, bmax = 0.f;
    bool hasMin = false, hasMax = false;
    float p[3], Psum, H;

    hbeta_eval(d, val, beta, p, Psum, H);
    float Hdiff = H - logU;
    for (int it = 0; it < NTRIES; ++it) {
        if (fabsf(Hdiff) < TOLR) break;
        if (Hdiff > 0.f) {
            bmin = beta; hasMin = true;
            beta = hasMax ? 0.5f * (beta + bmax) : beta * 2.f;
        } else {
            bmax = beta; hasMax = true;
            beta = hasMin ? 0.5f * (beta + bmin) : beta * 0.5f;
        }
        hbeta_eval(d, val, beta, p, Psum, H);
        Hdiff = H - logU;
    }

    float c[NCAT];
    #pragma unroll
    for (int cc = 0; cc < NCAT; ++cc) c[cc] = 0.f;
    #pragma unroll
    for (int t = 0; t < 3; ++t) {
        float pv = (val[t] && Psum > 0.f) ? __fdiv_rn(p[t], Psum) : 0.f;
        int lv = lb[t];
        #pragma unroll
        for (int cc = 0; cc < NCAT; ++cc)
            c[cc] += (lv == cc) ? pv : 0.f;
    }
    float simpson = 0.f;
    #pragma unroll
    for (int cc = 0; cc < NCAT; ++cc) {
        float tot = warp_sum(c[cc]);
        simpson += tot * tot;
    }
    if (H == 0.f) simpson -= 1.f;
    if (lane == 0) out[row] = __fdiv_rn(1.f, simpson);
}

// ------------------------------------------------------------------- launch
extern "C" void kernel_launch(void* const* d_in, const int* in_sizes, int n_in,
                              void* d_out, int out_size) {
    const float* x        = (const float*)d_in[0];
    const int*   batch_id = (const int*)d_in[1];
    float*       out      = (float*)d_out;

    constexpr int GEMM_SMEM = (BM * KPAD + BN * KPAD + BM + BN) * (int)sizeof(float);
    cudaFuncSetAttribute(gemm_d2_kernel,
                         cudaFuncAttributeMaxDynamicSharedMemorySize, GEMM_SMEM);

    gemm_d2_kernel<<<NTRI, 256, GEMM_SMEM>>>(x);
    select_kernel<<<NPTS, 256>>>(batch_id);
    beta_kernel<<<NPTS / 4, 128>>>(out);
}

// round 14
// speedup vs baseline: 1.1590x; 1.1590x over previous
#include <cuda_runtime.h>
#include <cstdint>
#include <cfloat>
#include <math.h>

#define NPTS 8192
#define DIM 64
#define KNN 90
#define NCAT 8
#define NTRIES 50
#define TOLR 1e-5f
#define SCAP 2048          // per-row candidate capacity

// scratch (device globals: allocation-free kernel_launch)
__device__ unsigned long long g_list[(size_t)NPTS * SCAP];  // 128 MB candidate lists
__device__ int   g_cnt[NPTS];
__device__ float g_T[NPTS];
__device__ float g_sq[NPTS];
__device__ float g_dist[NPTS * KNN];
__device__ int   g_lab[NPTS * KNN];

// ---------------------------------------------------------------- helpers
// XLA-emulating row norm: jnp.sum(x*x, -1): products individually rounded
// (no fma), float2-vectorized lane partials, then shfl tree. Warp-collective.
__device__ __forceinline__ float xla_row_sq(const float* rowp, int lane) {
    float x0 = rowp[2 * lane];
    float x1 = rowp[2 * lane + 1];
    float s = __fadd_rn(__fmul_rn(x0, x0), __fmul_rn(x1, x1));
    #pragma unroll
    for (int off = 16; off > 0; off >>= 1)
        s = __fadd_rn(s, __shfl_down_sync(0xffffffffu, s, off));
    return __shfl_sync(0xffffffffu, s, 0);
}

__device__ __forceinline__ void append_cand(int r, unsigned key, unsigned idx) {
    int pos = atomicAdd(&g_cnt[r], 1);
    if (pos < SCAP)
        g_list[(size_t)r * SCAP + pos] = ((unsigned long long)key << 32) | idx;
}

// ---------------------------------------------------------- sample kernel
// Per row: T[row] = 12th-smallest of 256 strided sampled d2 (pivot quality
// only — guarantees come from emit-kernel count validation). Also stores the
// XLA-tree sq[row] (bit-exact, used by the fallback) and zeroes the counter.
__global__ void __launch_bounds__(256) sample_kernel(const float* __restrict__ x) {
    __shared__ float xrow[DIM];
    __shared__ unsigned samp[256];

    const int row = blockIdx.x;
    const int tid = threadIdx.x;

    if (tid < DIM) xrow[tid] = x[(size_t)row * DIM + tid];
    if (tid == 0) g_cnt[row] = 0;
    __syncthreads();

    if (tid < 32) {
        float s = xla_row_sq(xrow, tid);
        if (tid == 0) g_sq[row] = s;
    }

    // sampled d2 at column tid*32 (plain arithmetic — pivot only)
    const int col = tid * 32;
    const float* xc = x + (size_t)col * DIM;
    float dot = 0.f, sc = 0.f, sr = 0.f;
    #pragma unroll
    for (int k = 0; k < DIM; ++k) {
        float a = xrow[k], b = xc[k];
        dot = fmaf(a, b, dot);
        sc  = fmaf(b, b, sc);
        sr  = fmaf(a, a, sr);
    }
    float d2 = fmaxf(sr + sc - 2.f * dot, 0.f);
    if (col == row) d2 = FLT_MAX;
    samp[tid] = __float_as_uint(d2);
    __syncthreads();

    // rank counting (no sort, no extra barriers); rank 11 -> 12th smallest
    unsigned mine = samp[tid];
    int r = 0;
    #pragma unroll 8
    for (int j = 0; j < 256; ++j) {
        unsigned o = samp[j];
        r += (o < mine) || (o == mine && j < tid);
    }
    if (r == 11) g_T[row] = __uint_as_float(mine);
}

// ---------------------------------------------------------------- GEMM stage
#define BM 128
#define BN 128
#define KPAD 65    // 64 + 1 pad: conflict-free LDS for strided frags
#define NTILE 64   // 8192 / 128
#define NTRI  2080 // NTILE*(NTILE+1)/2

// Triangular tiles only (bx >= by). d2 is bitwise symmetric (fmaf/fadd
// commute in their arguments, same ascending-k order), so each computed v
// serves both (gm, gn) and (gn, gm). Values are never stored: the epilogue
// appends (key, idx) for v <= T[row] directly to per-row candidate lists.
__global__ void __launch_bounds__(256, 2) gemm_d2_kernel(const float* __restrict__ x) {
    extern __shared__ float smem[];
    float* As   = smem;                    // [BM][KPAD]
    float* Bs   = smem + BM * KPAD;        // [BN][KPAD]
    float* sqA  = Bs + BN * KPAD;          // [BM]
    float* sqB  = sqA + BM;                // [BN]
    float* Trow = sqB + BN;                // [BM]
    float* Tcol = Trow + BM;               // [BN]

    // linear triangular index -> (by, bx), by <= bx
    const int t = blockIdx.x;
    int by = (int)((129.0 - sqrt(16641.0 - 8.0 * (double)t)) * 0.5);
    while (by > 0 && (by * (129 - by)) / 2 > t) --by;
    while (((by + 1) * (129 - (by + 1))) / 2 <= t) ++by;
    const int bx = by + (t - (by * (129 - by)) / 2);
    const bool mirror = (bx > by);

    const int tid = threadIdx.x;
    const int bm = by * BM;
    const int bn = bx * BN;

    // coalesced global load: float4 per thread
    const int c4 = tid & 15;
    const int rb = tid >> 4;
    #pragma unroll
    for (int it = 0; it < 8; ++it) {
        int r = rb + it * 16;
        float4 av = *reinterpret_cast<const float4*>(x + (size_t)(bm + r) * DIM + c4 * 4);
        float4 bv = *reinterpret_cast<const float4*>(x + (size_t)(bn + r) * DIM + c4 * 4);
        float* ap = As + r * KPAD + c4 * 4;
        ap[0] = av.x; ap[1] = av.y; ap[2] = av.z; ap[3] = av.w;
        float* bp = Bs + r * KPAD + c4 * 4;
        bp[0] = bv.x; bp[1] = bv.y; bp[2] = bv.z; bp[3] = bv.w;
    }
    // thresholds for both row ranges
    if (tid < BM) Trow[tid] = g_T[bm + tid];
    else          Tcol[tid - BM] = g_T[bn + tid - BM];
    __syncthreads();

    // norms with XLA-matching arithmetic (warp per row)
    {
        const int lane = tid & 31;
        const int wrp  = tid >> 5;
        #pragma unroll
        for (int it = 0; it < 16; ++it) {
            int r = wrp + it * 8;
            float sa = xla_row_sq(As + r * KPAD, lane);
            float sb = xla_row_sq(Bs + r * KPAD, lane);
            if (lane == 0) { sqA[r] = sa; sqB[r] = sb; }
        }
    }
    __syncthreads();

    // 8x8 micro-tile, strided mapping (row = ty+16i, col = tx+16j)
    const int tx = tid & 15;
    const int ty = tid >> 4;

    float acc[8][8];
    #pragma unroll
    for (int i = 0; i < 8; ++i)
        #pragma unroll
        for (int j = 0; j < 8; ++j) acc[i][j] = 0.f;

    // sequential ascending-k fp32 FFMA chain (reference-matching numerics)
    #pragma unroll 8
    for (int k = 0; k < DIM; ++k) {
        float a[8], b[8];
        #pragma unroll
        for (int i = 0; i < 8; ++i) a[i] = As[(ty + 16 * i) * KPAD + k];
        #pragma unroll
        for (int j = 0; j < 8; ++j) b[j] = Bs[(tx + 16 * j) * KPAD + k];
        #pragma unroll
        for (int i = 0; i < 8; ++i)
            #pragma unroll
            for (int j = 0; j < 8; ++j)
                acc[i][j] = fmaf(a[i], b[j], acc[i][j]);
    }

    // filtered append epilogue — no d2 stores
    #pragma unroll
    for (int i = 0; i < 8; ++i) {
        int m = ty + 16 * i;
        int gm = bm + m;
        float sm = sqA[m];
        float Tm = Trow[m];
        #pragma unroll
        for (int j = 0; j < 8; ++j) {
            int n = tx + 16 * j;
            int gn = bn + n;
            float v = __fsub_rn(__fadd_rn(sm, sqB[n]), __fmul_rn(2.f, acc[i][j]));
            v = fmaxf(v, 0.f);
            if (gm == gn) v = FLT_MAX;          // exclude self
            unsigned key = __float_as_uint(v);
            if (v <= Tm) append_cand(gm, key, (unsigned)gn);
            if (mirror && v <= Tcol[n]) append_cand(gn, key, (unsigned)gm);
        }
    }
}

// ------------------------------------------------------------- emit stage
// Per row: validate candidate list, bitonic sort by (key, idx) — exactly
// jax.lax.top_k order — and emit the first 90. If cnt >= 90 and no overflow,
// the list provably contains ALL keys <= T, hence the exact 90-NN.
__global__ void __launch_bounds__(256) emit_kernel(const int* __restrict__ batch_id) {
    __shared__ unsigned long long sl[SCAP];   // 16 KB

    const int row = blockIdx.x;
    const int tid = threadIdx.x;

    const int total = g_cnt[row];
    if (total < KNN || total > SCAP) return;   // fallback_kernel handles

    int sortN = 128;
    while (sortN < total) sortN <<= 1;

    const unsigned long long* lst = g_list + (size_t)row * SCAP;
    for (int i = tid; i < sortN; i += 256)
        sl[i] = (i < total) ? lst[i] : 0xFFFFFFFFFFFFFFFFull;
    __syncthreads();

    for (int k = 2; k <= sortN; k <<= 1) {
        for (int j = k >> 1; j > 0; j >>= 1) {
            for (int i = tid; i < sortN; i += 256) {
                int ix = i ^ j;
                if (ix > i) {
                    unsigned long long a = sl[i], b = sl[ix];
                    bool up = ((i & k) == 0);
                    if ((a > b) == up) { sl[i] = b; sl[ix] = a; }
                }
            }
            __syncthreads();
        }
    }

    if (tid < KNN) {
        unsigned long long v = sl[tid];
        unsigned key = (unsigned)(v >> 32);
        int idx = (int)(v & 0xFFFFFFFFu);
        g_dist[row * KNN + tid] = __fsqrt_rn(__uint_as_float(key));
        g_lab[row * KNN + tid]  = batch_id[idx];
    }
}

// --------------------------------------------------------- fallback stage
// Rows whose candidate list failed validation (expected ~2 per run, or zero):
// recompute the full d2 row BIT-EXACTLY (same fmaf order, XLA-tree sq, same
// epilogue rounding) and brute-force select.
__global__ void __launch_bounds__(256) fallback_kernel(const float* __restrict__ x,
                                                       const int* __restrict__ batch_id) {
    const int row = blockIdx.x;
    const int tid = threadIdx.x;
    {
        int total = g_cnt[row];
        if (total >= KNN && total <= SCAP) return;   // emit_kernel handled it
    }

    __shared__ unsigned skey[NPTS];   // 32 KB
    __shared__ float xrow[DIM];
    __shared__ float wv[8];
    __shared__ int   wj[8];

    if (tid < DIM) xrow[tid] = x[(size_t)row * DIM + tid];
    __syncthreads();

    const float sr = g_sq[row];
    for (int it = 0; it < 32; ++it) {
        int j = tid + it * 256;
        const float* xc = x + (size_t)j * DIM;
        float dot = 0.f;
        #pragma unroll
        for (int k = 0; k < DIM; ++k) dot = fmaf(xrow[k], xc[k], dot);
        float v = __fsub_rn(__fadd_rn(sr, g_sq[j]), __fmul_rn(2.f, dot));
        v = fmaxf(v, 0.f);
        if (j == row) v = FLT_MAX;
        skey[j] = __float_as_uint(v);
    }
    __syncthreads();

    const int lane = tid & 31;
    const int wid  = tid >> 5;
    for (int p = 0; p < KNN; ++p) {
        float bv = FLT_MAX; int bj = NPTS;
        #pragma unroll
        for (int it = 0; it < 32; ++it) {
            int j = it * 256 + tid;
            float v = __uint_as_float(skey[j]);
            if (v < bv) { bv = v; bj = j; }
        }
        #pragma unroll
        for (int off = 16; off > 0; off >>= 1) {
            float ov = __shfl_xor_sync(0xffffffffu, bv, off);
            int   oj = __shfl_xor_sync(0xffffffffu, bj, off);
            if (ov < bv || (ov == bv && oj < bj)) { bv = ov; bj = oj; }
        }
        if (lane == 0) { wv[wid] = bv; wj[wid] = bj; }
        __syncthreads();
        if (tid == 0) {
            float fv = wv[0]; int fj = wj[0];
            #pragma unroll
            for (int w = 1; w < 8; ++w)
                if (wv[w] < fv || (wv[w] == fv && wj[w] < fj)) { fv = wv[w]; fj = wj[w]; }
            skey[fj] = 0x7F7FFFFFu;   // FLT_MAX bits — remove winner
            g_dist[row * KNN + p] = __fsqrt_rn(fv);
            g_lab[row * KNN + p]  = batch_id[fj];
        }
        __syncthreads();
    }
}

// --------------------------------------------------------- beta search stage
__device__ __forceinline__ float warp_sum(float v) {
    #pragma unroll
    for (int o = 16; o > 0; o >>= 1) v += __shfl_xor_sync(0xffffffffu, v, o);
    return v;
}

// FTZ exp: XLA compiles GPU f32 with flush-to-zero — exp results that would be
// subnormal flush to 0. Load-bearing: rows whose solution beta sits past the
// subnormal cliff hit Psum==0 -> H==0 sentinel in the reference.
__device__ __forceinline__ float exp_ftz(float a) {
    float v = expf(a);
    if (v < 1.17549435e-38f) v = 0.f;
    return v;
}

__device__ __forceinline__ void hbeta_eval(const float d[3], const bool val[3],
                                           float beta, float p[3],
                                           float& Psum, float& H) {
    float ls = 0.f, lds = 0.f;
    #pragma unroll
    for (int t = 0; t < 3; ++t) {
        float pv = val[t] ? exp_ftz(-d[t] * beta) : 0.f;
        p[t] = pv;
        ls  += pv;
        lds += d[t] * pv;
    }
    Psum   = warp_sum(ls);
    float S = warp_sum(lds);
    H = (Psum > 0.f) ? (logf(Psum) + beta * __fdiv_rn(S, Psum)) : 0.f;
}

__global__ void __launch_bounds__(128) beta_kernel(float* __restrict__ out) {
    const int warp = threadIdx.x >> 5;
    const int lane = threadIdx.x & 31;
    const int row  = blockIdx.x * 4 + warp;

    float d[3]; int lb[3]; bool val[3];
    #pragma unroll
    for (int t = 0; t < 3; ++t) {
        int kk = lane + 32 * t;
        val[t] = (kk < KNN);
        d[t]  = val[t] ? g_dist[row * KNN + kk] : 0.f;
        lb[t] = val[t] ? g_lab[row * KNN + kk]  : -1;
    }

    const float logU = logf(30.0f);
    float beta = 1.f, bmin = 0.f, bmax = 0.f;
    bool hasMin = false, hasMax = false;
    float p[3], Psum, H;

    hbeta_eval(d, val, beta, p, Psum, H);
    float Hdiff = H - logU;
    for (int it = 0; it < NTRIES; ++it) {
        if (fabsf(Hdiff) < TOLR) break;
        if (Hdiff > 0.f) {
            bmin = beta; hasMin = true;
            beta = hasMax ? 0.5f * (beta + bmax) : beta * 2.f;
        } else {
            bmax = beta; hasMax = true;
            beta = hasMin ? 0.5f * (beta + bmin) : beta * 0.5f;
        }
        hbeta_eval(d, val, beta, p, Psum, H);
        Hdiff = H - logU;
    }

    float c[NCAT];
    #pragma unroll
    for (int cc = 0; cc < NCAT; ++cc) c[cc] = 0.f;
    #pragma unroll
    for (int t = 0; t < 3; ++t) {
        float pv = (val[t] && Psum > 0.f) ? __fdiv_rn(p[t], Psum) : 0.f;
        int lv = lb[t];
        #pragma unroll
        for (int cc = 0; cc < NCAT; ++cc)
            c[cc] += (lv == cc) ? pv : 0.f;
    }
    float simpson = 0.f;
    #pragma unroll
    for (int cc = 0; cc < NCAT; ++cc) {
        float tot = warp_sum(c[cc]);
        simpson += tot * tot;
    }
    if (H == 0.f) simpson -= 1.f;
    if (lane == 0) out[row] = __fdiv_rn(1.f, simpson);
}

// ------------------------------------------------------------------- launch
extern "C" void kernel_launch(void* const* d_in, const int* in_sizes, int n_in,
                              void* d_out, int out_size) {
    const float* x        = (const float*)d_in[0];
    const int*   batch_id = (const int*)d_in[1];
    float*       out      = (float*)d_out;

    constexpr int GEMM_SMEM = (BM * KPAD + BN * KPAD + 4 * BM) * (int)sizeof(float);
    cudaFuncSetAttribute(gemm_d2_kernel,
                         cudaFuncAttributeMaxDynamicSharedMemorySize, GEMM_SMEM);

    sample_kernel<<<NPTS, 256>>>(x);
    gemm_d2_kernel<<<NTRI, 256, GEMM_SMEM>>>(x);
    emit_kernel<<<NPTS, 256>>>(batch_id);
    fallback_kernel<<<NPTS, 256>>>(x, batch_id);
    beta_kernel<<<NPTS / 4, 128>>>(out);
}

// round 15
// speedup vs baseline: 2.4060x; 2.0759x over previous
#include <cuda_runtime.h>
#include <cstdint>
#include <cfloat>
#include <math.h>

#define NPTS 8192
#define DIM 64
#define KNN 90
#define NCAT 8
#define NTRIES 50
#define TOLR 1e-5f
#define CCAP 2048    // candidate capacity

// scratch (device globals: allocation-free kernel_launch)
__device__ float g_d2[(size_t)NPTS * NPTS];   // 256 MB pairwise d2 (diagonal = FLT_MAX)
__device__ float g_dist[NPTS * KNN];
__device__ int   g_lab[NPTS * KNN];

// ---------------------------------------------------------------- GEMM stage
#define BM 128
#define BN 128
#define KPAD 65    // 64 + 1 pad: conflict-free LDS for strided frags
#define TPITCH 129 // transpose-stage pitch

// XLA-emulating row norm: jnp.sum(x*x, -1): products individually rounded
// (no fma), float2-vectorized lane partials, then shfl tree.
__device__ __forceinline__ float xla_row_sq(const float* rowp, int lane) {
    float x0 = rowp[2 * lane];
    float x1 = rowp[2 * lane + 1];
    float s = __fadd_rn(__fmul_rn(x0, x0), __fmul_rn(x1, x1));
    #pragma unroll
    for (int off = 16; off > 0; off >>= 1)
        s = __fadd_rn(s, __shfl_down_sync(0xffffffffu, s, off));
    return __shfl_sync(0xffffffffu, s, 0);
}

// Upper-triangle tiles only (bx >= by): d2 is bitwise symmetric
// (fmaf(a,b,c)==fmaf(b,a,c); fadd commutes; same ascending-k order), so the
// off-diagonal mirror tile is written from an smem-staged transpose.
__global__ void __launch_bounds__(256, 2) gemm_d2_kernel(const float* __restrict__ x) {
    extern __shared__ float smem[];
    float* As  = smem;                    // [BM][KPAD]
    float* Bs  = smem + BM * KPAD;        // [BN][KPAD]
    float* sqA = Bs + BN * KPAD;          // [BM]
    float* sqB = sqA + BM;                // [BN]
    float* Ts  = smem;                    // transpose stage, reuses As+Bs

    const int bx = blockIdx.x;
    const int by = blockIdx.y;
    if (by > bx) return;                  // lower triangle via mirror
    const bool mirror = (bx > by);

    const int tid = threadIdx.x;
    const int bm = by * BM;
    const int bn = bx * BN;

    // coalesced global load: float4 per thread, 16 threads cover one 64-col row
    const int c4 = tid & 15;
    const int rb = tid >> 4;
    #pragma unroll
    for (int it = 0; it < 8; ++it) {
        int r = rb + it * 16;
        float4 av = *reinterpret_cast<const float4*>(x + (size_t)(bm + r) * DIM + c4 * 4);
        float4 bv = *reinterpret_cast<const float4*>(x + (size_t)(bn + r) * DIM + c4 * 4);
        float* ap = As + r * KPAD + c4 * 4;
        ap[0] = av.x; ap[1] = av.y; ap[2] = av.z; ap[3] = av.w;
        float* bp = Bs + r * KPAD + c4 * 4;
        bp[0] = bv.x; bp[1] = bv.y; bp[2] = bv.z; bp[3] = bv.w;
    }
    __syncthreads();

    // norms with XLA-matching arithmetic (warp per row)
    {
        const int lane = tid & 31;
        const int wrp  = tid >> 5;
        #pragma unroll
        for (int it = 0; it < 16; ++it) {
            int r = wrp + it * 8;
            float sa = xla_row_sq(As + r * KPAD, lane);
            float sb = xla_row_sq(Bs + r * KPAD, lane);
            if (lane == 0) { sqA[r] = sa; sqB[r] = sb; }
        }
    }
    __syncthreads();

    // 8x8 micro-tile, strided mapping (row = ty+16i, col = tx+16j)
    const int tx = tid & 15;
    const int ty = tid >> 4;

    float acc[8][8];
    #pragma unroll
    for (int i = 0; i < 8; ++i)
        #pragma unroll
        for (int j = 0; j < 8; ++j) acc[i][j] = 0.f;

    // sequential ascending-k fp32 FFMA chain (reference-matching numerics)
    #pragma unroll 8
    for (int k = 0; k < DIM; ++k) {
        float a[8], b[8];
        #pragma unroll
        for (int i = 0; i < 8; ++i) a[i] = As[(ty + 16 * i) * KPAD + k];
        #pragma unroll
        for (int j = 0; j < 8; ++j) b[j] = Bs[(tx + 16 * j) * KPAD + k];
        #pragma unroll
        for (int i = 0; i < 8; ++i)
            #pragma unroll
            for (int j = 0; j < 8; ++j)
                acc[i][j] = fmaf(a[i], b[j], acc[i][j]);
    }
    __syncthreads();   // all warps done reading As/Bs before Ts staging

    #pragma unroll
    for (int i = 0; i < 8; ++i) {
        int m = ty + 16 * i;
        int gm = bm + m;
        float sm = sqA[m];
        float* orow = g_d2 + (size_t)gm * NPTS + bn;
        #pragma unroll
        for (int j = 0; j < 8; ++j) {
            int n = tx + 16 * j;
            float v = __fsub_rn(__fadd_rn(sm, sqB[n]), __fmul_rn(2.f, acc[i][j]));
            v = fmaxf(v, 0.f);
            if (gm == bn + n) v = FLT_MAX;     // exclude self (diag tiles only)
            orow[n] = v;
            if (mirror) Ts[n * TPITCH + m] = v;
        }
    }

    if (mirror) {
        __syncthreads();
        #pragma unroll
        for (int q = 0; q < 16; ++q) {
            int idx = tid + q * 256;
            int r   = idx >> 5;
            int cc  = idx & 31;
            const float* tp = Ts + r * TPITCH + cc * 4;
            float4 v;
            v.x = tp[0]; v.y = tp[1]; v.z = tp[2]; v.w = tp[3];
            *reinterpret_cast<float4*>(g_d2 + (size_t)(bn + r) * NPTS + bm + cc * 4) = v;
        }
    }
}

// ------------------------------------------------------------- select stage
// one block per row. Row loaded once into registers. Pivot: per-warp shfl
// bitonic sort of 32 samples (no barriers) -> warp 0 rank-counts the 64 warp
// heads -> exact 8th-smallest sample T0 (E[cands]~255) and ~32nd T1 (retry).
// Gather: 2-pass ballot compaction, ONE shared atomic per warp. Emit: bitonic
// sort by (key, idx) == exact jax.lax.top_k order; count-validated; brute
// fallback for degenerate data.
__global__ void __launch_bounds__(256) select_kernel(const int* __restrict__ batch_id) {
    __shared__ unsigned long long candB[CCAP];   // 16 KB
    __shared__ unsigned heads[64];
    __shared__ unsigned s_T0, s_T1, s_cnt;
    __shared__ float wv[8];
    __shared__ int   wj[8];

    const int row  = blockIdx.x;
    const int tid  = threadIdx.x;
    const int lane = tid & 31;
    const int wid  = tid >> 5;

    // single coalesced DRAM pass into registers (MLP = 8)
    const uint4* rp = reinterpret_cast<const uint4*>(g_d2 + (size_t)row * NPTS);
    uint4 kreg[8];
    #pragma unroll
    for (int it = 0; it < 8; ++it) kreg[it] = rp[tid + it * 256];

    // --- per-warp shfl bitonic sort of 32 samples (ascending by lane) ---
    {
        unsigned v = kreg[0].x;
        #pragma unroll
        for (int k = 2; k <= 32; k <<= 1) {
            #pragma unroll
            for (int j = k >> 1; j > 0; j >>= 1) {
                unsigned o = __shfl_xor_sync(0xffffffffu, v, j);
                bool dir = ((lane & k) == 0) || (k == 32);
                bool keepMin = (((lane & j) == 0) == dir);
                v = keepMin ? umin(v, o) : umax(v, o);
            }
        }
        if (lane < 8) heads[wid * 8 + lane] = v;   // warp's 8 smallest
    }
    __syncthreads();

    // --- warp 0: rank-count the 64 heads; global 8th smallest is exact ---
    if (wid == 0) {
        unsigned a = heads[lane];
        unsigned b = heads[lane + 32];
        int ra = 0, rb = 0;
        #pragma unroll 8
        for (int j = 0; j < 64; ++j) {
            unsigned o = heads[j];
            ra += (o < a) || (o == a && j < lane);
            rb += (o < b) || (o == b && j < lane + 32);
        }
        if (ra == 7)  s_T0 = a;
        if (rb == 7)  s_T0 = b;
        if (ra == 31) s_T1 = a;
        if (rb == 31) s_T1 = b;
    }
    __syncthreads();

    // --- gather attempts: 2-pass ballot compaction, 1 atomic per warp ---
    bool ok = false;
    unsigned total = 0;
    for (int attempt = 0; attempt < 2 && !ok; ++attempt) {
        unsigned T = attempt ? s_T1 : s_T0;
        if (tid == 0) s_cnt = 0;
        __syncthreads();

        // pass 1: count this warp's candidates
        unsigned wn = 0;
        #pragma unroll
        for (int it = 0; it < 8; ++it) {
            unsigned kk[4] = { kreg[it].x, kreg[it].y, kreg[it].z, kreg[it].w };
            #pragma unroll
            for (int c = 0; c < 4; ++c)
                wn += __popc(__ballot_sync(0xffffffffu, kk[c] <= T));
        }
        unsigned base = 0;
        if (lane == 0) base = atomicAdd(&s_cnt, wn);
        base = __shfl_sync(0xffffffffu, base, 0);

        // pass 2: compacted write at warp base (deterministic within warp;
        // cross-warp order canonicalized by the sort)
        unsigned cur = base;
        #pragma unroll
        for (int it = 0; it < 8; ++it) {
            unsigned kk[4] = { kreg[it].x, kreg[it].y, kreg[it].z, kreg[it].w };
            #pragma unroll
            for (int c = 0; c < 4; ++c) {
                unsigned key = kk[c];
                bool pred = (key <= T);
                unsigned mask = __ballot_sync(0xffffffffu, pred);
                unsigned rnk = __popc(mask & ((1u << lane) - 1u));
                if (pred && cur + rnk < CCAP) {
                    unsigned j = 4u * (unsigned)(tid + it * 256) + (unsigned)c;
                    candB[cur + rnk] = ((unsigned long long)key << 32) | j;
                }
                cur += __popc(mask);
            }
        }
        __syncthreads();
        total = s_cnt;
        ok = (total >= KNN && total <= CCAP);
        __syncthreads();
    }

    if (ok) {
        // pad to pow2 and bitonic sort ascending by (key, idx)
        int sortN = 128;
        while (sortN < (int)total) sortN <<= 1;
        for (int i = tid; i < sortN; i += 256)
            if (i >= (int)total) candB[i] = 0xFFFFFFFFFFFFFFFFull;
        __syncthreads();
        for (int k = 2; k <= sortN; k <<= 1) {
            for (int j = k >> 1; j > 0; j >>= 1) {
                for (int i = tid; i < sortN; i += 256) {
                    int ix = i ^ j;
                    if (ix > i) {
                        unsigned long long a = candB[i], b = candB[ix];
                        bool up = ((i & k) == 0);
                        if ((a > b) == up) { candB[i] = b; candB[ix] = a; }
                    }
                }
                __syncthreads();
            }
        }
        if (tid < KNN) {
            unsigned long long v = candB[tid];
            unsigned key = (unsigned)(v >> 32);
            int idx = (int)(v & 0xFFFFFFFFu);
            g_dist[row * KNN + tid] = __fsqrt_rn(__uint_as_float(key));
            g_lab[row * KNN + tid]  = batch_id[idx];
        }
        return;
    }

    // --- brute-force fallback (degenerate data only; never taken) ---
    for (int p = 0; p < KNN; ++p) {
        float bv = FLT_MAX; int bj = NPTS;
        #pragma unroll
        for (int it = 0; it < 8; ++it) {
            unsigned kk[4] = { kreg[it].x, kreg[it].y, kreg[it].z, kreg[it].w };
            #pragma unroll
            for (int c = 0; c < 4; ++c) {
                float v = __uint_as_float(kk[c]);
                int j = 4 * (tid + it * 256) + c;
                if (v < bv || (v == bv && j < bj)) { bv = v; bj = j; }
            }
        }
        #pragma unroll
        for (int off = 16; off > 0; off >>= 1) {
            float ov = __shfl_xor_sync(0xffffffffu, bv, off);
            int   oj = __shfl_xor_sync(0xffffffffu, bj, off);
            if (ov < bv || (ov == bv && oj < bj)) { bv = ov; bj = oj; }
        }
        if (lane == 0) { wv[wid] = bv; wj[wid] = bj; }
        __syncthreads();
        if (tid == 0) {
            float fv = wv[0]; int fj = wj[0];
            #pragma unroll
            for (int w = 1; w < 8; ++w)
                if (wv[w] < fv || (wv[w] == fv && wj[w] < fj)) { fv = wv[w]; fj = wj[w]; }
            wj[0] = fj;
            g_dist[row * KNN + p] = __fsqrt_rn(fv);
            g_lab[row * KNN + p]  = batch_id[fj];
        }
        __syncthreads();
        int fj = wj[0];
        int own_t  = (fj >> 2) & 255;
        int own_it = (fj >> 2) >> 8;
        int own_c  = fj & 3;
        if (tid == own_t) {
            #pragma unroll
            for (int it = 0; it < 8; ++it) {
                if (it == own_it) {
                    if (own_c == 0) kreg[it].x = 0x7F7FFFFFu;
                    if (own_c == 1) kreg[it].y = 0x7F7FFFFFu;
                    if (own_c == 2) kreg[it].z = 0x7F7FFFFFu;
                    if (own_c == 3) kreg[it].w = 0x7F7FFFFFu;
                }
            }
        }
        __syncthreads();
    }
}

// --------------------------------------------------------- beta search stage
__device__ __forceinline__ float warp_sum(float v) {
    #pragma unroll
    for (int o = 16; o > 0; o >>= 1) v += __shfl_xor_sync(0xffffffffu, v, o);
    return v;
}

// FTZ exp: XLA compiles GPU f32 with flush-to-zero — exp results that would be
// subnormal flush to 0. DO NOT change expf: sentinel rows' bisection converges
// onto the flush cliff, so final H is ulp-sensitive to the exp implementation.
__device__ __forceinline__ float exp_ftz(float a) {
    float v = expf(a);
    if (v < 1.17549435e-38f) v = 0.f;
    return v;
}

__device__ __forceinline__ void hbeta_eval(const float d[3], const bool val[3],
                                           float beta, float p[3],
                                           float& Psum, float& H) {
    float ls = 0.f, lds = 0.f;
    #pragma unroll
    for (int t = 0; t < 3; ++t) {
        float pv = val[t] ? exp_ftz(-d[t] * beta) : 0.f;
        p[t] = pv;
        ls  += pv;
        lds += d[t] * pv;
    }
    Psum   = warp_sum(ls);
    float S = warp_sum(lds);
    H = (Psum > 0.f) ? (logf(Psum) + beta * __fdiv_rn(S, Psum)) : 0.f;
}

__global__ void __launch_bounds__(128) beta_kernel(float* __restrict__ out) {
    const int warp = threadIdx.x >> 5;
    const int lane = threadIdx.x & 31;
    const int row  = blockIdx.x * 4 + warp;

    float d[3]; int lb[3]; bool val[3];
    #pragma unroll
    for (int t = 0; t < 3; ++t) {
        int kk = lane + 32 * t;
        val[t] = (kk < KNN);
        d[t]  = val[t] ? g_dist[row * KNN + kk] : 0.f;
        lb[t] = val[t] ? g_lab[row * KNN + kk]  : -1;
    }

    const float logU = logf(30.0f);
    float beta = 1.f, bmin = 0.f, bmax = 0.f;
    bool hasMin = false, hasMax = false;
    float p[3], Psum, H;

    hbeta_eval(d, val, beta, p, Psum, H);
    float Hdiff = H - logU;
    for (int it = 0; it < NTRIES; ++it) {
        if (fabsf(Hdiff) < TOLR) break;
        if (Hdiff > 0.f) {
            bmin = beta; hasMin = true;
            beta = hasMax ? 0.5f * (beta + bmax) : beta * 2.f;
        } else {
            bmax = beta; hasMax = true;
            beta = hasMin ? 0.5f * (beta + bmin) : beta * 0.5f;
        }
        hbeta_eval(d, val, beta, p, Psum, H);
        Hdiff = H - logU;
    }

    float c[NCAT];
    #pragma unroll
    for (int cc = 0; cc < NCAT; ++cc) c[cc] = 0.f;
    #pragma unroll
    for (int t = 0; t < 3; ++t) {
        float pv = (val[t] && Psum > 0.f) ? __fdiv_rn(p[t], Psum) : 0.f;
        int lv = lb[t];
        #pragma unroll
        for (int cc = 0; cc < NCAT; ++cc)
            c[cc] += (lv == cc) ? pv : 0.f;
    }
    float simpson = 0.f;
    #pragma unroll
    for (int cc = 0; cc < NCAT; ++cc) {
        float tot = warp_sum(c[cc]);
        simpson += tot * tot;
    }
    if (H == 0.f) simpson -= 1.f;
    if (lane == 0) out[row] = __fdiv_rn(1.f, simpson);
}

// ------------------------------------------------------------------- launch
extern "C" void kernel_launch(void* const* d_in, const int* in_sizes, int n_in,
                              void* d_out, int out_size) {
    const float* x        = (const float*)d_in[0];
    const int*   batch_id = (const int*)d_in[1];
    float*       out      = (float*)d_out;

    constexpr int GEMM_SMEM = (BM * KPAD + BN * KPAD + BM + BN) * (int)sizeof(float);
    cudaFuncSetAttribute(gemm_d2_kernel,
                         cudaFuncAttributeMaxDynamicSharedMemorySize, GEMM_SMEM);

    gemm_d2_kernel<<<dim3(NPTS / BN, NPTS / BM), 256, GEMM_SMEM>>>(x);
    select_kernel<<<NPTS, 256>>>(batch_id);
    beta_kernel<<<NPTS / 4, 128>>>(out);
}